// round 15
// baseline (speedup 1.0000x reference)
#include <cuda_runtime.h>

// Problem-fixed sizes: 100k nodes, 1.25M edges, feats 64 -> 64 -> 32
#define NV_MAX 100000
#define NE_MAX 1250000

// Scratch (module-load allocated; no runtime allocation)
__device__ int   g_cnt[NV_MAX];        // per-dst edge counts / fill cursors
__device__ int   g_row[NV_MAX + 1];    // CSR row pointers (by dst)
__device__ int   g_part[128];          // per-block scan partials
__device__ int   g_adj[NE_MAX];        // CSR adjacency: src node per slot
__device__ float g_hn [NV_MAX * 64];   // layer-1 neighbor mean (64-dim)
__device__ float g_h1 [NV_MAX * 64];   // layer-1 activations
__device__ float g_z  [NV_MAX * 32];   // z = h1 @ Wn2 (pre-transformed, 32-dim)
__device__ float g_hn2[NV_MAX * 32];   // layer-2 neighbor mean of z (32-dim)
__device__ int   g_is64;               // 1 if index buffers are int64-layout

// ---------------------------------------------------------------------------
// Zero counters + detect index dtype (thread 0): little-endian int64 with
// values < 2^31 has all odd 32-bit words zero; random int32 ids never do.
// ---------------------------------------------------------------------------
__global__ void zero_counts(const int* __restrict__ idx, int nV) {
    int i = blockIdx.x * blockDim.x + threadIdx.x;
    if (i < nV) g_cnt[i] = 0;
    if (blockIdx.x == 0 && threadIdx.x == 0) {
        int allz = 1;
        #pragma unroll
        for (int j = 1; j < 64; j += 2)
            if (idx[j] != 0) allz = 0;
        g_is64 = allz;
    }
}

__device__ __forceinline__ int load_idx(const void* p, int e, int nV) {
    int v = g_is64 ? (int)((const long long*)p)[e] : ((const int*)p)[e];
    return min(max(v, 0), nV - 1);
}

__global__ void hist_kernel(const void* __restrict__ dst, int nE, int nV) {
    int e = blockIdx.x * blockDim.x + threadIdx.x;
    if (e < nE) atomicAdd(&g_cnt[load_idx(dst, e, nV)], 1);
}

// ---------------------------------------------------------------------------
// Two-level exclusive scan of g_cnt -> g_row
// ---------------------------------------------------------------------------
__global__ void scan_block(int nV) {
    __shared__ int wsum[32];
    int gid  = blockIdx.x * 1024 + threadIdx.x;
    int lane = threadIdx.x & 31;
    int w    = threadIdx.x >> 5;

    int v = (gid < nV) ? g_cnt[gid] : 0;
    int s = v;
    #pragma unroll
    for (int o = 1; o < 32; o <<= 1) {
        int t = __shfl_up_sync(0xFFFFFFFFu, s, o);
        if (lane >= o) s += t;
    }
    if (lane == 31) wsum[w] = s;
    __syncthreads();
    if (w == 0) {
        int t = wsum[lane];
        int ss = t;
        #pragma unroll
        for (int o = 1; o < 32; o <<= 1) {
            int u = __shfl_up_sync(0xFFFFFFFFu, ss, o);
            if (lane >= o) ss += u;
        }
        wsum[lane] = ss - t;
    }
    __syncthreads();
    int incl = s + wsum[w];
    if (gid < nV) g_row[gid] = incl - v;
    if (threadIdx.x == 1023) g_part[blockIdx.x] = incl;
}

__global__ void scan_part(int nb, int nV) {
    __shared__ int wsum[4];
    int lane = threadIdx.x & 31;
    int w    = threadIdx.x >> 5;

    int v = (threadIdx.x < nb) ? g_part[threadIdx.x] : 0;
    int s = v;
    #pragma unroll
    for (int o = 1; o < 32; o <<= 1) {
        int t = __shfl_up_sync(0xFFFFFFFFu, s, o);
        if (lane >= o) s += t;
    }
    if (lane == 31) wsum[w] = s;
    __syncthreads();
    int off = 0;
    for (int i = 0; i < w; ++i) off += wsum[i];
    int incl = s + off;
    if (threadIdx.x < nb) g_part[threadIdx.x] = incl - v;
    if (threadIdx.x == nb - 1) g_row[nV] = incl;
}

__global__ void scan_add(int nV) {
    int gid = blockIdx.x * 1024 + threadIdx.x;
    if (gid < nV) {
        g_row[gid] += g_part[blockIdx.x];
        g_cnt[gid] = 0;
    }
}

__global__ void fill_kernel(const void* __restrict__ src,
                            const void* __restrict__ dst, int nE, int nV) {
    int e = blockIdx.x * blockDim.x + threadIdx.x;
    if (e >= nE) return;
    int d = load_idx(dst, e, nV);
    int p = g_row[d] + atomicAdd(&g_cnt[d], 1);
    if (p < NE_MAX) g_adj[p] = load_idx(src, e, nV);
}

// ---------------------------------------------------------------------------
// Layer-1 aggregation: one warp per node; 8 lanes per edge, each lane loads
// TWO float4 chunks (c and c+8) of the 64-float row -> 4 edges in flight,
// 8 independent LDG.128 per warp-iteration. Slot combine via shfl_xor(8,16).
// ---------------------------------------------------------------------------
__global__ void agg64_kernel(const float* __restrict__ xin, int nV) {
    int warp = (blockIdx.x * blockDim.x + threadIdx.x) >> 5;
    int lane = threadIdx.x & 31;
    if (warp >= nV) return;

    int beg = g_row[warp];
    int end = g_row[warp + 1];

    const float4* f4 = reinterpret_cast<const float4*>(xin);
    int slot = lane >> 3;      // 0..3: edge slot
    int c    = lane & 7;       // chunk index: handles c and c+8

    float ax = 0.f, ay = 0.f, az = 0.f, aw = 0.f;
    float bx = 0.f, by = 0.f, bz = 0.f, bw = 0.f;
    for (int j = beg + slot; j < end; j += 4) {
        int s = g_adj[j];
        const float4* r = f4 + (size_t)s * 16;
        float4 v1 = __ldg(r + c);
        float4 v2 = __ldg(r + c + 8);
        ax += v1.x; ay += v1.y; az += v1.z; aw += v1.w;
        bx += v2.x; by += v2.y; bz += v2.z; bw += v2.w;
    }
    #pragma unroll
    for (int m = 8; m <= 16; m <<= 1) {
        ax += __shfl_xor_sync(0xFFFFFFFFu, ax, m);
        ay += __shfl_xor_sync(0xFFFFFFFFu, ay, m);
        az += __shfl_xor_sync(0xFFFFFFFFu, az, m);
        aw += __shfl_xor_sync(0xFFFFFFFFu, aw, m);
        bx += __shfl_xor_sync(0xFFFFFFFFu, bx, m);
        by += __shfl_xor_sync(0xFFFFFFFFu, by, m);
        bz += __shfl_xor_sync(0xFFFFFFFFu, bz, m);
        bw += __shfl_xor_sync(0xFFFFFFFFu, bw, m);
    }
    if (lane < 8) {
        float inv = (end > beg) ? (1.0f / (float)(end - beg)) : 0.0f;
        float4* o = reinterpret_cast<float4*>(g_hn) + (size_t)warp * 16;
        o[c]     = make_float4(ax * inv, ay * inv, az * inv, aw * inv);
        o[c + 8] = make_float4(bx * inv, by * inv, bz * inv, bw * inv);
    }
}

// ---------------------------------------------------------------------------
// Layer-2 aggregation over pre-transformed z (32-dim): quarter-warp per
// edge (8 x float4 per row), 4 edges in flight, shfl_xor(8,16) combine.
// ---------------------------------------------------------------------------
__global__ void agg32_kernel(int nV) {
    int warp = (blockIdx.x * blockDim.x + threadIdx.x) >> 5;
    int lane = threadIdx.x & 31;
    if (warp >= nV) return;

    int beg = g_row[warp];
    int end = g_row[warp + 1];

    const float4* f4 = reinterpret_cast<const float4*>(g_z);
    int sub = lane >> 3;
    int c   = lane & 7;

    float ax = 0.f, ay = 0.f, az = 0.f, aw = 0.f;
    for (int j = beg + sub; j < end; j += 4) {
        int s = g_adj[j];
        float4 v = __ldg(f4 + (size_t)s * 8 + c);
        ax += v.x; ay += v.y; az += v.z; aw += v.w;
    }
    #pragma unroll
    for (int m = 8; m <= 16; m <<= 1) {
        ax += __shfl_xor_sync(0xFFFFFFFFu, ax, m);
        ay += __shfl_xor_sync(0xFFFFFFFFu, ay, m);
        az += __shfl_xor_sync(0xFFFFFFFFu, az, m);
        aw += __shfl_xor_sync(0xFFFFFFFFu, aw, m);
    }
    if (lane < 8) {
        float inv = (end > beg) ? (1.0f / (float)(end - beg)) : 0.0f;
        reinterpret_cast<float4*>(g_hn2)[(size_t)warp * 8 + c] =
            make_float4(ax * inv, ay * inv, az * inv, aw * inv);
    }
}

// ---------------------------------------------------------------------------
// Node kernel, layer 1: h1 = relu( x @ Ws1 + g_hn @ Wn1 + b1 )
// Packed fp32 math (fma.rn.f32x2 / FFMA2): inputs staged TRANSPOSED in
// sT[k][node] (stride 18, conflict-free fill mapping) so a node-pair loads
// as one LDS.64; 2 FFMA2 per k per thread cover 4 nodes. 16 nodes in
// flight, 64 nodes per block, 256 threads = 64 out-channels x 4 y-slots.
// ---------------------------------------------------------------------------
#define ST_STRIDE 18

__global__ void node1_kernel(const float* __restrict__ x,
                             const float* __restrict__ Ws,
                             const float* __restrict__ Wn,
                             const float* __restrict__ b,
                             int nV) {
    __shared__ float sW[128 * 64];                 // rows 0..63 Ws, 64..127 Wn
    __shared__ float sB[64];
    __shared__ __align__(8) float sT[128 * ST_STRIDE];  // [k][node], transposed

    for (int i = threadIdx.x; i < 64 * 64; i += 256) {
        sW[i]           = Ws[i];
        sW[64 * 64 + i] = Wn[i];
    }
    if (threadIdx.x < 64) sB[threadIdx.x] = b[threadIdx.x];
    __syncthreads();

    int o  = threadIdx.x & 63;
    int y  = threadIdx.x >> 6;          // 0..3
    int fn = threadIdx.x & 15;          // fill: node 0..15
    int fq = threadIdx.x >> 4;          // fill: k-octet 0..15
    int base = blockIdx.x * 64;

    // packed bias {b,b}
    unsigned long long bias2;
    {
        unsigned int bu = __float_as_uint(sB[o]);
        asm("mov.b64 %0, {%1, %1};" : "=l"(bias2) : "r"(bu));
    }

    #pragma unroll 1
    for (int r = 0; r < 4; ++r) {       // 4 rounds x 16 nodes
        // ---- fill sT transposed: thread (fn, fq) loads 8 floats of node fn
        {
            int n = base + r * 16 + fn;
            float4 u0 = make_float4(0.f, 0.f, 0.f, 0.f), u1 = u0;
            if (n < nV) {
                const float4* srcp = (fq < 8)
                    ? reinterpret_cast<const float4*>(x    + (size_t)n * 64 + fq * 8)
                    : reinterpret_cast<const float4*>(g_hn + (size_t)n * 64 + (fq - 8) * 8);
                u0 = __ldg(srcp);
                u1 = __ldg(srcp + 1);
            }
            int k0 = fq * 8;
            sT[(k0 + 0) * ST_STRIDE + fn] = u0.x;
            sT[(k0 + 1) * ST_STRIDE + fn] = u0.y;
            sT[(k0 + 2) * ST_STRIDE + fn] = u0.z;
            sT[(k0 + 3) * ST_STRIDE + fn] = u0.w;
            sT[(k0 + 4) * ST_STRIDE + fn] = u1.x;
            sT[(k0 + 5) * ST_STRIDE + fn] = u1.y;
            sT[(k0 + 6) * ST_STRIDE + fn] = u1.z;
            sT[(k0 + 7) * ST_STRIDE + fn] = u1.w;
        }
        __syncthreads();

        // ---- compute: pairs {2y,2y+1} and {2y+8,2y+9}
        unsigned long long acc01 = bias2, acc23 = bias2;
        int p0 = 2 * y, p1 = 2 * y + 8;
        #pragma unroll
        for (int k = 0; k < 128; ++k) {
            unsigned int wu = __float_as_uint(sW[k * 64 + o]);
            unsigned long long w2;
            asm("mov.b64 %0, {%1, %1};" : "=l"(w2) : "r"(wu));
            unsigned long long i01 =
                *reinterpret_cast<const unsigned long long*>(&sT[k * ST_STRIDE + p0]);
            unsigned long long i23 =
                *reinterpret_cast<const unsigned long long*>(&sT[k * ST_STRIDE + p1]);
            asm("fma.rn.f32x2 %0, %1, %2, %0;" : "+l"(acc01) : "l"(i01), "l"(w2));
            asm("fma.rn.f32x2 %0, %1, %2, %0;" : "+l"(acc23) : "l"(i23), "l"(w2));
        }

        unsigned int r0, r1, r2, r3;
        asm("mov.b64 {%0, %1}, %2;" : "=r"(r0), "=r"(r1) : "l"(acc01));
        asm("mov.b64 {%0, %1}, %2;" : "=r"(r2), "=r"(r3) : "l"(acc23));

        int n0 = base + r * 16 + p0;
        int n2 = base + r * 16 + p1;
        if (n0 < nV)     g_h1[(size_t)n0 * 64 + o]       = fmaxf(__uint_as_float(r0), 0.0f);
        if (n0 + 1 < nV) g_h1[(size_t)(n0 + 1) * 64 + o] = fmaxf(__uint_as_float(r1), 0.0f);
        if (n2 < nV)     g_h1[(size_t)n2 * 64 + o]       = fmaxf(__uint_as_float(r2), 0.0f);
        if (n2 + 1 < nV) g_h1[(size_t)(n2 + 1) * 64 + o] = fmaxf(__uint_as_float(r3), 0.0f);
        __syncthreads();
    }
}

// ---------------------------------------------------------------------------
// z-transform: z = h1 @ Wn2  (100k x 64 @ 64 x 32)
// ---------------------------------------------------------------------------
__global__ void ztrans_kernel(const float* __restrict__ Wn, int nV) {
    __shared__ float sW[64 * 32];
    __shared__ float sIn[16][64];

    for (int i = threadIdx.x; i < 64 * 32; i += 256) sW[i] = Wn[i];
    __syncthreads();

    int o = threadIdx.x & 31;
    int y = threadIdx.x >> 5;       // 0..7
    int base = blockIdx.x * 64;

    #pragma unroll 1
    for (int r = 0; r < 4; ++r) {
        int n0 = base + r * 16 + y;
        int n1 = n0 + 8;
        if (n0 < nV) {
            sIn[y][o]          = g_h1[(size_t)n0 * 64 + o];
            sIn[y][o + 32]     = g_h1[(size_t)n0 * 64 + o + 32];
        }
        if (n1 < nV) {
            sIn[y + 8][o]      = g_h1[(size_t)n1 * 64 + o];
            sIn[y + 8][o + 32] = g_h1[(size_t)n1 * 64 + o + 32];
        }
        __syncthreads();
        float a0 = 0.f, a1 = 0.f;
        #pragma unroll
        for (int k = 0; k < 64; ++k) {
            float w = sW[k * 32 + o];
            a0 = fmaf(sIn[y][k],     w, a0);
            a1 = fmaf(sIn[y + 8][k], w, a1);
        }
        if (n0 < nV) g_z[(size_t)n0 * 32 + o] = a0;
        if (n1 < nV) g_z[(size_t)n1 * 32 + o] = a1;
        __syncthreads();
    }
}

// ---------------------------------------------------------------------------
// Node kernel, layer 2: out = h1 @ Ws2 + g_hn2 + b2  (K=64)
// ---------------------------------------------------------------------------
__global__ void node2_kernel(const float* __restrict__ Ws,
                             const float* __restrict__ b,
                             float* __restrict__ out,
                             int nV) {
    __shared__ float sW[64 * 32];
    __shared__ float sB[32];
    __shared__ float sIn[16][64];

    for (int i = threadIdx.x; i < 64 * 32; i += 256) sW[i] = Ws[i];
    if (threadIdx.x < 32) sB[threadIdx.x] = b[threadIdx.x];
    __syncthreads();

    int o = threadIdx.x & 31;
    int y = threadIdx.x >> 5;
    int base = blockIdx.x * 64;

    #pragma unroll 1
    for (int r = 0; r < 4; ++r) {
        int n0 = base + r * 16 + y;
        int n1 = n0 + 8;
        if (n0 < nV) {
            sIn[y][o]          = g_h1[(size_t)n0 * 64 + o];
            sIn[y][o + 32]     = g_h1[(size_t)n0 * 64 + o + 32];
        }
        if (n1 < nV) {
            sIn[y + 8][o]      = g_h1[(size_t)n1 * 64 + o];
            sIn[y + 8][o + 32] = g_h1[(size_t)n1 * 64 + o + 32];
        }
        __syncthreads();
        float a0 = sB[o], a1 = a0;
        #pragma unroll
        for (int k = 0; k < 64; ++k) {
            float w = sW[k * 32 + o];
            a0 = fmaf(sIn[y][k],     w, a0);
            a1 = fmaf(sIn[y + 8][k], w, a1);
        }
        if (n0 < nV) out[(size_t)n0 * 32 + o] = a0 + g_hn2[(size_t)n0 * 32 + o];
        if (n1 < nV) out[(size_t)n1 * 32 + o] = a1 + g_hn2[(size_t)n1 * 32 + o];
        __syncthreads();
    }
}

// ---------------------------------------------------------------------------
// Launch (kernel launches only — fully graph-capturable)
// ---------------------------------------------------------------------------
extern "C" void kernel_launch(void* const* d_in, const int* in_sizes, int n_in,
                              void* d_out, int out_size) {
    const float* x    = (const float*)d_in[0];
    const void*  src  = d_in[1];
    const void*  dst  = d_in[2];
    const float* Ws1  = (const float*)d_in[3];
    const float* Wn1  = (const float*)d_in[4];
    const float* b1   = (const float*)d_in[5];
    const float* Ws2  = (const float*)d_in[6];
    const float* Wn2  = (const float*)d_in[7];
    const float* b2   = (const float*)d_in[8];
    float*       out  = (float*)d_out;

    int nV = in_sizes[0] / 64;
    int nE = in_sizes[1];

    int eb = (nE + 255) / 256;
    int vb = (nV + 255) / 256;
    int sb = (nV + 1023) / 1024;     // <=128 scan blocks

    zero_counts<<<vb, 256>>>((const int*)dst, nV);
    hist_kernel<<<eb, 256>>>(dst, nE, nV);
    scan_block<<<sb, 1024>>>(nV);
    scan_part<<<1, 128>>>(sb, nV);
    scan_add<<<sb, 1024>>>(nV);
    fill_kernel<<<eb, 256>>>(src, dst, nE, nV);

    int ab = (nV * 32 + 255) / 256;  // one warp per node
    int nb = (nV + 63) / 64;

    agg64_kernel<<<ab, 256>>>(x, nV);
    node1_kernel<<<nb, 256>>>(x, Ws1, Wn1, b1, nV);
    ztrans_kernel<<<nb, 256>>>(Wn2, nV);
    agg32_kernel<<<ab, 256>>>(nV);
    node2_kernel<<<nb, 256>>>(Ws2, b2, out, nV);
}

// round 17
// speedup vs baseline: 1.0567x; 1.0567x over previous
#include <cuda_runtime.h>

// Problem-fixed sizes: 100k nodes, 1.25M edges, feats 64 -> 64 -> 32
#define NV_MAX 100000
#define NE_MAX 1250000

// Scratch (module-load allocated; no runtime allocation)
__device__ int   g_cnt[NV_MAX];        // per-dst edge counts / fill cursors
__device__ int   g_row[NV_MAX + 1];    // CSR row pointers (by dst)
__device__ int   g_part[128];          // per-block scan partials
__device__ int   g_adj[NE_MAX];        // CSR adjacency: src node per slot
__device__ float g_hn [NV_MAX * 64];   // layer-1 neighbor mean (64-dim)
__device__ float g_h1 [NV_MAX * 64];   // layer-1 activations
__device__ float g_z  [NV_MAX * 32];   // z = h1 @ Wn2 (pre-transformed, 32-dim)
__device__ int   g_is64;               // 1 if index buffers are int64-layout

// ---------------------------------------------------------------------------
// Zero counters + detect index dtype (thread 0)
// ---------------------------------------------------------------------------
__global__ void zero_counts(const int* __restrict__ idx, int nV) {
    int i = blockIdx.x * blockDim.x + threadIdx.x;
    if (i < nV) g_cnt[i] = 0;
    if (blockIdx.x == 0 && threadIdx.x == 0) {
        int allz = 1;
        #pragma unroll
        for (int j = 1; j < 64; j += 2)
            if (idx[j] != 0) allz = 0;
        g_is64 = allz;
    }
}

__device__ __forceinline__ int load_idx(const void* p, int e, int nV) {
    int v = g_is64 ? (int)((const long long*)p)[e] : ((const int*)p)[e];
    return min(max(v, 0), nV - 1);
}

__global__ void hist_kernel(const void* __restrict__ dst, int nE, int nV) {
    int e = blockIdx.x * blockDim.x + threadIdx.x;
    if (e < nE) atomicAdd(&g_cnt[load_idx(dst, e, nV)], 1);
}

// ---------------------------------------------------------------------------
// Two-level exclusive scan of g_cnt -> g_row
// ---------------------------------------------------------------------------
__global__ void scan_block(int nV) {
    __shared__ int wsum[32];
    int gid  = blockIdx.x * 1024 + threadIdx.x;
    int lane = threadIdx.x & 31;
    int w    = threadIdx.x >> 5;

    int v = (gid < nV) ? g_cnt[gid] : 0;
    int s = v;
    #pragma unroll
    for (int o = 1; o < 32; o <<= 1) {
        int t = __shfl_up_sync(0xFFFFFFFFu, s, o);
        if (lane >= o) s += t;
    }
    if (lane == 31) wsum[w] = s;
    __syncthreads();
    if (w == 0) {
        int t = wsum[lane];
        int ss = t;
        #pragma unroll
        for (int o = 1; o < 32; o <<= 1) {
            int u = __shfl_up_sync(0xFFFFFFFFu, ss, o);
            if (lane >= o) ss += u;
        }
        wsum[lane] = ss - t;
    }
    __syncthreads();
    int incl = s + wsum[w];
    if (gid < nV) g_row[gid] = incl - v;
    if (threadIdx.x == 1023) g_part[blockIdx.x] = incl;
}

__global__ void scan_part(int nb, int nV) {
    __shared__ int wsum[4];
    int lane = threadIdx.x & 31;
    int w    = threadIdx.x >> 5;

    int v = (threadIdx.x < nb) ? g_part[threadIdx.x] : 0;
    int s = v;
    #pragma unroll
    for (int o = 1; o < 32; o <<= 1) {
        int t = __shfl_up_sync(0xFFFFFFFFu, s, o);
        if (lane >= o) s += t;
    }
    if (lane == 31) wsum[w] = s;
    __syncthreads();
    int off = 0;
    for (int i = 0; i < w; ++i) off += wsum[i];
    int incl = s + off;
    if (threadIdx.x < nb) g_part[threadIdx.x] = incl - v;
    if (threadIdx.x == nb - 1) g_row[nV] = incl;
}

__global__ void scan_add(int nV) {
    int gid = blockIdx.x * 1024 + threadIdx.x;
    if (gid < nV) {
        g_row[gid] += g_part[blockIdx.x];
        g_cnt[gid] = 0;
    }
}

__global__ void fill_kernel(const void* __restrict__ src,
                            const void* __restrict__ dst, int nE, int nV) {
    int e = blockIdx.x * blockDim.x + threadIdx.x;
    if (e >= nE) return;
    int d = load_idx(dst, e, nV);
    int p = g_row[d] + atomicAdd(&g_cnt[d], 1);
    if (p < NE_MAX) g_adj[p] = load_idx(src, e, nV);
}

// ---------------------------------------------------------------------------
// Layer-1 aggregation (R9 measured-good form): one warp per node, half-warp
// per edge (16 x float4 per 64-float row), two edges in flight, shfl_xor(16).
// ---------------------------------------------------------------------------
__global__ void agg64_kernel(const float* __restrict__ xin, int nV) {
    int warp = (blockIdx.x * blockDim.x + threadIdx.x) >> 5;
    int lane = threadIdx.x & 31;
    if (warp >= nV) return;

    int beg = g_row[warp];
    int end = g_row[warp + 1];

    const float4* f4 = reinterpret_cast<const float4*>(xin);
    int half = lane >> 4;
    int c    = lane & 15;

    float ax = 0.f, ay = 0.f, az = 0.f, aw = 0.f;
    for (int j = beg + half; j < end; j += 2) {
        int s = g_adj[j];
        float4 v = __ldg(f4 + (size_t)s * 16 + c);
        ax += v.x; ay += v.y; az += v.z; aw += v.w;
    }
    ax += __shfl_xor_sync(0xFFFFFFFFu, ax, 16);
    ay += __shfl_xor_sync(0xFFFFFFFFu, ay, 16);
    az += __shfl_xor_sync(0xFFFFFFFFu, az, 16);
    aw += __shfl_xor_sync(0xFFFFFFFFu, aw, 16);

    if (half == 0) {
        float inv = (end > beg) ? (1.0f / (float)(end - beg)) : 0.0f;
        reinterpret_cast<float4*>(g_hn)[(size_t)warp * 16 + c] =
            make_float4(ax * inv, ay * inv, az * inv, aw * inv);
    }
}

// ---------------------------------------------------------------------------
// Node kernel, layer 1 (R9 measured-good form): scalar 4-accumulator,
// 4 FMA per sW LDS. 16 nodes in flight, 64 nodes per block.
// ---------------------------------------------------------------------------
__global__ void node1_kernel(const float* __restrict__ x,
                             const float* __restrict__ Ws,
                             const float* __restrict__ Wn,
                             const float* __restrict__ b,
                             int nV) {
    __shared__ float sW[128 * 64];
    __shared__ float sB[64];
    __shared__ float sIn[16][128];

    for (int i = threadIdx.x; i < 64 * 64; i += 256) {
        sW[i]           = Ws[i];
        sW[64 * 64 + i] = Wn[i];
    }
    if (threadIdx.x < 64) sB[threadIdx.x] = b[threadIdx.x];
    __syncthreads();

    int o = threadIdx.x & 63;
    int y = threadIdx.x >> 6;
    int base = blockIdx.x * 64;

    #pragma unroll 1
    for (int r = 0; r < 4; ++r) {
        #pragma unroll
        for (int i = 0; i < 4; ++i) {
            int n = base + r * 16 + y + 4 * i;
            if (n < nV) {
                sIn[y + 4 * i][o]      = x   [(size_t)n * 64 + o];
                sIn[y + 4 * i][64 + o] = g_hn[(size_t)n * 64 + o];
            }
        }
        __syncthreads();
        float a0 = sB[o], a1 = a0, a2 = a0, a3 = a0;
        #pragma unroll
        for (int k = 0; k < 128; ++k) {
            float w = sW[k * 64 + o];
            a0 = fmaf(sIn[y][k],      w, a0);
            a1 = fmaf(sIn[y + 4][k],  w, a1);
            a2 = fmaf(sIn[y + 8][k],  w, a2);
            a3 = fmaf(sIn[y + 12][k], w, a3);
        }
        int n0 = base + r * 16 + y;
        if (n0 < nV)      g_h1[(size_t)n0 * 64 + o]        = fmaxf(a0, 0.0f);
        if (n0 + 4 < nV)  g_h1[(size_t)(n0 + 4) * 64 + o]  = fmaxf(a1, 0.0f);
        if (n0 + 8 < nV)  g_h1[(size_t)(n0 + 8) * 64 + o]  = fmaxf(a2, 0.0f);
        if (n0 + 12 < nV) g_h1[(size_t)(n0 + 12) * 64 + o] = fmaxf(a3, 0.0f);
        __syncthreads();
    }
}

// ---------------------------------------------------------------------------
// z-transform: z = h1 @ Wn2  (100k x 64 @ 64 x 32)
// ---------------------------------------------------------------------------
__global__ void ztrans_kernel(const float* __restrict__ Wn, int nV) {
    __shared__ float sW[64 * 32];
    __shared__ float sIn[16][64];

    for (int i = threadIdx.x; i < 64 * 32; i += 256) sW[i] = Wn[i];
    __syncthreads();

    int o = threadIdx.x & 31;
    int y = threadIdx.x >> 5;
    int base = blockIdx.x * 64;

    #pragma unroll 1
    for (int r = 0; r < 4; ++r) {
        int n0 = base + r * 16 + y;
        int n1 = n0 + 8;
        if (n0 < nV) {
            sIn[y][o]          = g_h1[(size_t)n0 * 64 + o];
            sIn[y][o + 32]     = g_h1[(size_t)n0 * 64 + o + 32];
        }
        if (n1 < nV) {
            sIn[y + 8][o]      = g_h1[(size_t)n1 * 64 + o];
            sIn[y + 8][o + 32] = g_h1[(size_t)n1 * 64 + o + 32];
        }
        __syncthreads();
        float a0 = 0.f, a1 = 0.f;
        #pragma unroll
        for (int k = 0; k < 64; ++k) {
            float w = sW[k * 32 + o];
            a0 = fmaf(sIn[y][k],     w, a0);
            a1 = fmaf(sIn[y + 8][k], w, a1);
        }
        if (n0 < nV) g_z[(size_t)n0 * 32 + o] = a0;
        if (n1 < nV) g_z[(size_t)n1 * 32 + o] = a1;
        __syncthreads();
    }
}

// ---------------------------------------------------------------------------
// FUSED layer-2 tail: one warp per node.
//   phase 1: gather hn2 = mean of z[src] rows (quarter-warp per edge, as the
//            old agg32), result staged in per-warp smem sZ
//   phase 2: stage the node's h1 row in smem, then lane l computes
//            out[n][l] = b2[l] + hn2[l] + sum_k h1[n][k] * Ws2[k][l]
// The gather's memory latency overlaps with the GEMM issue stream; saves the
// g_hn2 global round-trip and one kernel launch vs separate agg32 + node2.
// ---------------------------------------------------------------------------
__global__ void l2fused_kernel(const float* __restrict__ Ws,
                               const float* __restrict__ b,
                               float* __restrict__ out, int nV) {
    __shared__ float sW[64 * 32];
    __shared__ float sB[32];
    __shared__ __align__(16) float sH[8][64];   // per-warp h1 row
    __shared__ __align__(16) float sZ[8][32];   // per-warp hn2

    for (int i = threadIdx.x; i < 64 * 32; i += 256) sW[i] = Ws[i];
    if (threadIdx.x < 32) sB[threadIdx.x] = b[threadIdx.x];
    __syncthreads();

    int warp = (blockIdx.x * blockDim.x + threadIdx.x) >> 5;
    int lane = threadIdx.x & 31;
    int w    = (threadIdx.x >> 5) & 7;
    if (warp >= nV) return;

    int beg = g_row[warp];
    int end = g_row[warp + 1];

    // --- phase 1: gather mean of z rows (32-dim) ---
    const float4* f4 = reinterpret_cast<const float4*>(g_z);
    int sub = lane >> 3;       // 0..3: edge slot
    int c   = lane & 7;        // float4 chunk within 32-float row

    float ax = 0.f, ay = 0.f, az = 0.f, aw = 0.f;
    for (int j = beg + sub; j < end; j += 4) {
        int s = g_adj[j];
        float4 v = __ldg(f4 + (size_t)s * 8 + c);
        ax += v.x; ay += v.y; az += v.z; aw += v.w;
    }
    #pragma unroll
    for (int m = 8; m <= 16; m <<= 1) {
        ax += __shfl_xor_sync(0xFFFFFFFFu, ax, m);
        ay += __shfl_xor_sync(0xFFFFFFFFu, ay, m);
        az += __shfl_xor_sync(0xFFFFFFFFu, az, m);
        aw += __shfl_xor_sync(0xFFFFFFFFu, aw, m);
    }
    if (lane < 8) {
        float inv = (end > beg) ? (1.0f / (float)(end - beg)) : 0.0f;
        reinterpret_cast<float4*>(sZ[w])[c] =
            make_float4(ax * inv, ay * inv, az * inv, aw * inv);
    }

    // --- stage this node's h1 row (64 floats = 16 x float4) ---
    if (lane < 16)
        reinterpret_cast<float4*>(sH[w])[lane] =
            __ldg(reinterpret_cast<const float4*>(g_h1 + (size_t)warp * 64) + lane);
    __syncwarp();

    // --- phase 2: GEMM K=64, 32 outputs (one per lane) ---
    float acc = sB[lane] + sZ[w][lane];
    #pragma unroll
    for (int k = 0; k < 64; ++k)
        acc = fmaf(sH[w][k], sW[k * 32 + lane], acc);
    out[(size_t)warp * 32 + lane] = acc;
}

// ---------------------------------------------------------------------------
// Launch (kernel launches only — fully graph-capturable)
// ---------------------------------------------------------------------------
extern "C" void kernel_launch(void* const* d_in, const int* in_sizes, int n_in,
                              void* d_out, int out_size) {
    const float* x    = (const float*)d_in[0];
    const void*  src  = d_in[1];
    const void*  dst  = d_in[2];
    const float* Ws1  = (const float*)d_in[3];
    const float* Wn1  = (const float*)d_in[4];
    const float* b1   = (const float*)d_in[5];
    const float* Ws2  = (const float*)d_in[6];
    const float* Wn2  = (const float*)d_in[7];
    const float* b2   = (const float*)d_in[8];
    float*       out  = (float*)d_out;

    int nV = in_sizes[0] / 64;
    int nE = in_sizes[1];

    int eb = (nE + 255) / 256;
    int vb = (nV + 255) / 256;
    int sb = (nV + 1023) / 1024;     // <=128 scan blocks

    zero_counts<<<vb, 256>>>((const int*)dst, nV);
    hist_kernel<<<eb, 256>>>(dst, nE, nV);
    scan_block<<<sb, 1024>>>(nV);
    scan_part<<<1, 128>>>(sb, nV);
    scan_add<<<sb, 1024>>>(nV);
    fill_kernel<<<eb, 256>>>(src, dst, nE, nV);

    int ab = (nV * 32 + 255) / 256;  // one warp per node
    int nb = (nV + 63) / 64;

    agg64_kernel<<<ab, 256>>>(x, nV);
    node1_kernel<<<nb, 256>>>(x, Ws1, Wn1, b1, nV);
    ztrans_kernel<<<nb, 256>>>(Wn2, nV);
    l2fused_kernel<<<ab, 256>>>(Ws2, b2, out, nV);
}